// round 3
// baseline (speedup 1.0000x reference)
#include <cuda_runtime.h>
#include <cstdint>

#define B_SZ   1024
#define HID    512
#define FEAT   32
#define CIN    4
#define KCONV  30
#define STRIDEC 6
#define LIN    924
#define TSTEPS 150
#define KDD    40
#define NSTEPS 10
#define G4     2048          // 4*HID
#define BH     (B_SZ*HID)    // 524288

// ---------------- device scratch (static; no allocations) ----------------
__device__ float g_seq[TSTEPS * B_SZ * FEAT];   // conv output, [t][b][f]
__device__ float g_W0p[G4 * 544];               // packed+permuted [Wih0|Whh0], tf32-rounded
__device__ float g_W1p[G4 * 1024];              // packed+permuted [Wih1|Whh1]
__device__ float g_b0p[G4];
__device__ float g_b1p[G4];
__device__ float g_state[6 * BH];               // h0[0],h0[1],c0,h1[0],h1[1],c1
__device__ float g_y[B_SZ * FEAT];
__device__ float g_fut[NSTEPS * B_SZ * FEAT];   // [s][b][f]
__device__ float g_decwT[HID * FEAT];           // dec_w transposed [j][f]

__device__ __forceinline__ float to_tf32(float x) {
    float r;
    asm("cvt.rna.tf32.f32 %0, %1;" : "=f"(r) : "f"(x));
    return r;
}

__device__ __forceinline__ void mma_tf32(float* d, const unsigned* a, const unsigned* b) {
    asm volatile(
        "mma.sync.aligned.m16n8k8.row.col.f32.tf32.tf32.f32 "
        "{%0,%1,%2,%3}, {%4,%5,%6,%7}, {%8,%9}, {%0,%1,%2,%3};"
        : "+f"(d[0]), "+f"(d[1]), "+f"(d[2]), "+f"(d[3])
        : "r"(a[0]), "r"(a[1]), "r"(a[2]), "r"(a[3]), "r"(b[0]), "r"(b[1]));
}

// ---------------- init ----------------
__global__ void zero_state_kernel() {
    int i = blockIdx.x * blockDim.x + threadIdx.x;
    if (i < 6 * BH) g_state[i] = 0.f;
}

// ---------------- encoder conv: [B,4,924] -> seq[t][b][f], relu ----------------
__global__ void conv_kernel(const float* __restrict__ x,
                            const float* __restrict__ w,
                            const float* __restrict__ bias) {
    __shared__ float xs[CIN * LIN];           // 3696 floats
    __shared__ float ws[FEAT * CIN * KCONV];  // 3840 floats
    __shared__ float bs[FEAT];
    int b = blockIdx.x;
    for (int i = threadIdx.x; i < CIN * LIN; i += blockDim.x) xs[i] = x[b * CIN * LIN + i];
    for (int i = threadIdx.x; i < FEAT * CIN * KCONV; i += blockDim.x) ws[i] = w[i];
    if (threadIdx.x < FEAT) bs[threadIdx.x] = bias[threadIdx.x];
    __syncthreads();
    for (int o = threadIdx.x; o < FEAT * TSTEPS; o += blockDim.x) {
        int f = o / TSTEPS, t = o % TSTEPS;
        float acc = bs[f];
        #pragma unroll
        for (int c = 0; c < CIN; c++) {
            const float* xr = xs + c * LIN + t * STRIDEC;
            const float* wr = ws + (f * CIN + c) * KCONV;
            #pragma unroll
            for (int k = 0; k < KCONV; k++) acc += xr[k] * wr[k];
        }
        g_seq[(t * B_SZ + b) * FEAT + f] = fmaxf(acc, 0.f);
    }
}

// ---------------- weight packing (gate-permuted, tf32-rounded) ----------------
// packed row p: blk = p>>7, gate = (p>>5)&3, u = p&31  ->  original g = gate*512 + blk*32 + u
__global__ void pack_w0_kernel(const float* __restrict__ Wih, const float* __restrict__ Whh,
                               const float* __restrict__ bih, const float* __restrict__ bhh) {
    int idx = blockIdx.x * blockDim.x + threadIdx.x;
    if (idx >= G4 * 544) return;
    int p = idx / 544, k = idx - p * 544;
    int blk = p >> 7, gt = (p >> 5) & 3, u = p & 31;
    int g = gt * HID + blk * 32 + u;
    float v = (k < FEAT) ? Wih[g * FEAT + k] : Whh[g * HID + (k - FEAT)];
    g_W0p[idx] = to_tf32(v);
    if (k == 0) g_b0p[p] = bih[g] + bhh[g];
}

__global__ void pack_w1_kernel(const float* __restrict__ Wih, const float* __restrict__ Whh,
                               const float* __restrict__ bih, const float* __restrict__ bhh) {
    int idx = blockIdx.x * blockDim.x + threadIdx.x;
    if (idx >= G4 * 1024) return;
    int p = idx >> 10, k = idx & 1023;
    int blk = p >> 7, gt = (p >> 5) & 3, u = p & 31;
    int g = gt * HID + blk * 32 + u;
    float v = (k < HID) ? Wih[g * HID + k] : Whh[g * HID + (k - HID)];
    g_W1p[idx] = to_tf32(v);
    if (k == 0) g_b1p[p] = bih[g] + bhh[g];
}

__global__ void pack_dec_kernel(const float* __restrict__ dec_w) {
    int i = blockIdx.x * blockDim.x + threadIdx.x;  // 512*32
    if (i >= HID * FEAT) return;
    int j = i >> 5, f = i & 31;
    g_decwT[j * FEAT + f] = dec_w[f * HID + j];
}

// ---------------- fused LSTM step: gates = [x|h] @ Wp^T + b, then cell update ----------------
// C tile 128x128 per CTA, grid (16 gate-tiles, 8 batch-tiles), 256 threads (8 warps 2x4),
// warp tile 64x32, tf32 m16n8k8, K streamed in 32-wide tiles, double buffered.
__global__ void __launch_bounds__(256, 1)
lstm_step_kernel(const float* __restrict__ x1, int w1,
                 const float* __restrict__ h_in, int K,
                 const float* __restrict__ Wp, const float* __restrict__ bp,
                 float* __restrict__ c_state, float* __restrict__ h_out) {
    extern __shared__ float smem[];
    // stage s: A at smem + s*9216, B at smem + s*9216 + 4608 ; row stride 36
    const int tid = threadIdx.x;
    const int lane = tid & 31;
    const int warp = tid >> 5;
    const int warpM = warp >> 2;   // 0..1
    const int warpN = warp & 3;    // 0..3
    const int bN = blockIdx.x;     // gate tile (128 packed gate rows)
    const int bM = blockIdx.y;     // batch tile (128 rows)

    const int lrow = tid >> 3;        // 0..31
    const int lc4  = (tid & 7) * 4;   // 0,4,...,28

    float acc[4][4][4];
    #pragma unroll
    for (int a = 0; a < 4; a++)
        #pragma unroll
        for (int b = 0; b < 4; b++)
            #pragma unroll
            for (int c = 0; c < 4; c++) acc[a][b][c] = 0.f;

    const int NT = K >> 5;

    auto loadA = [&](int kt, float4* ra) {
        #pragma unroll
        for (int rr = 0; rr < 4; rr++) {
            int row = lrow + rr * 32;
            int rg = bM * 128 + row;
            int k0 = kt * 32 + lc4;
            const float* src = (k0 < w1) ? (x1 + (size_t)rg * w1 + k0)
                                         : (h_in + (size_t)rg * HID + (k0 - w1));
            ra[rr] = *(const float4*)src;
        }
    };
    auto loadB = [&](int kt, float4* rb) {
        #pragma unroll
        for (int rr = 0; rr < 4; rr++) {
            int row = lrow + rr * 32;
            int rg = bN * 128 + row;
            rb[rr] = *(const float4*)(Wp + (size_t)rg * K + kt * 32 + lc4);
        }
    };
    auto storeA = [&](float* As, const float4* ra) {
        #pragma unroll
        for (int rr = 0; rr < 4; rr++) {
            int row = lrow + rr * 32;
            float4 v = ra[rr];
            v.x = to_tf32(v.x); v.y = to_tf32(v.y); v.z = to_tf32(v.z); v.w = to_tf32(v.w);
            *(float4*)(As + row * 36 + lc4) = v;
        }
    };
    auto storeB = [&](float* Bs, const float4* rb) {
        #pragma unroll
        for (int rr = 0; rr < 4; rr++) {
            int row = lrow + rr * 32;
            *(float4*)(Bs + row * 36 + lc4) = rb[rr];
        }
    };
    auto compute = [&](const float* As, const float* Bs) {
        #pragma unroll
        for (int kk = 0; kk < 4; kk++) {
            unsigned af[4][4];
            #pragma unroll
            for (int mt = 0; mt < 4; mt++) {
                int r = warpM * 64 + mt * 16 + (lane >> 2);
                int c = kk * 8 + (lane & 3);
                af[mt][0] = __float_as_uint(As[r * 36 + c]);
                af[mt][1] = __float_as_uint(As[(r + 8) * 36 + c]);
                af[mt][2] = __float_as_uint(As[r * 36 + c + 4]);
                af[mt][3] = __float_as_uint(As[(r + 8) * 36 + c + 4]);
            }
            unsigned bf[4][2];
            #pragma unroll
            for (int nt = 0; nt < 4; nt++) {
                int n = warpN * 32 + nt * 8 + (lane >> 2);
                bf[nt][0] = __float_as_uint(Bs[n * 36 + kk * 8 + (lane & 3)]);
                bf[nt][1] = __float_as_uint(Bs[n * 36 + kk * 8 + (lane & 3) + 4]);
            }
            #pragma unroll
            for (int mt = 0; mt < 4; mt++)
                #pragma unroll
                for (int nt = 0; nt < 4; nt++)
                    mma_tf32(acc[mt][nt], af[mt], bf[nt]);
        }
    };

    // prologue
    {
        float4 ra[4], rb[4];
        loadA(0, ra); loadB(0, rb);
        storeA(smem, ra); storeB(smem + 4608, rb);
    }
    __syncthreads();

    int buf = 0;
    for (int kt = 0; kt < NT; kt++) {
        float4 ra[4], rb[4];
        bool more = (kt + 1 < NT);
        if (more) { loadA(kt + 1, ra); loadB(kt + 1, rb); }
        const float* As = smem + buf * 9216;
        const float* Bs = As + 4608;
        compute(As, Bs);
        if (more) {
            float* An = smem + (buf ^ 1) * 9216;
            storeA(An, ra); storeB(An + 4608, rb);
            __syncthreads();
            buf ^= 1;
        }
    }

    // epilogue: gates -> smem (stride 132), then fused LSTM cell update
    __syncthreads();
    float* gs = smem;
    #pragma unroll
    for (int mt = 0; mt < 4; mt++) {
        #pragma unroll
        for (int nt = 0; nt < 4; nt++) {
            int r0 = warpM * 64 + mt * 16 + (lane >> 2);
            int c0 = warpN * 32 + nt * 8 + (lane & 3) * 2;
            gs[r0 * 132 + c0]       = acc[mt][nt][0];
            gs[r0 * 132 + c0 + 1]   = acc[mt][nt][1];
            gs[(r0 + 8) * 132 + c0]     = acc[mt][nt][2];
            gs[(r0 + 8) * 132 + c0 + 1] = acc[mt][nt][3];
        }
    }
    __syncthreads();

    int u = tid & 31;
    int brow0 = tid >> 5;
    float bi = bp[bN * 128 + u];
    float bf_ = bp[bN * 128 + 32 + u];
    float bg = bp[bN * 128 + 64 + u];
    float bo = bp[bN * 128 + 96 + u];
    int j = bN * 32 + u;   // hidden unit index
    #pragma unroll
    for (int i = 0; i < 16; i++) {
        int bl = brow0 + i * 8;
        int bglob = bM * 128 + bl;
        float gi = gs[bl * 132 + u] + bi;
        float gf = gs[bl * 132 + 32 + u] + bf_;
        float gg = gs[bl * 132 + 64 + u] + bg;
        float go = gs[bl * 132 + 96 + u] + bo;
        float iv = 1.f / (1.f + __expf(-gi));
        float fv = 1.f / (1.f + __expf(-gf));
        float gv = tanhf(gg);
        float ov = 1.f / (1.f + __expf(-go));
        int idx = bglob * HID + j;
        float cn = fv * c_state[idx] + iv * gv;
        c_state[idx] = cn;
        h_out[idx] = ov * tanhf(cn);
    }
}

// ---------------- decoder projection: y = h @ dec_w^T + dec_b ----------------
__global__ void dec_out_kernel(const float* __restrict__ h, float* __restrict__ y,
                               const float* __restrict__ dec_b, int slot) {
    int g = blockIdx.x * blockDim.x + threadIdx.x;  // 32768
    int b = g >> 5, f = g & 31;
    float acc = dec_b[f];
    const float* hr = h + b * HID;
    #pragma unroll 8
    for (int j = 0; j < HID; j++) acc += hr[j] * g_decwT[j * FEAT + f];
    y[b * FEAT + f] = acc;
    if (slot >= 0) g_fut[(slot * B_SZ + b) * FEAT + f] = acc;
}

// ---------------- conv transpose: fut[b,f,10] * w[f,1,40] -> out[b,1,49] ----------------
__global__ void deconv_kernel(const float* __restrict__ dw, float* __restrict__ out) {
    __shared__ float futb[NSTEPS * FEAT];
    __shared__ float dws[FEAT * KDD];
    int b = blockIdx.x;
    for (int i = threadIdx.x; i < NSTEPS * FEAT; i += blockDim.x) {
        int t = i >> 5, f = i & 31;
        futb[i] = g_fut[(t * B_SZ + b) * FEAT + f];
    }
    for (int i = threadIdx.x; i < FEAT * KDD; i += blockDim.x) dws[i] = dw[i];
    __syncthreads();
    int jj = threadIdx.x;
    if (jj < NSTEPS + KDD - 1) {
        float acc = 0.f;
        #pragma unroll
        for (int t = 0; t < NSTEPS; t++) {
            int k = jj - t;
            if (k >= 0 && k < KDD) {
                #pragma unroll
                for (int f = 0; f < FEAT; f++) acc += futb[t * FEAT + f] * dws[f * KDD + k];
            }
        }
        out[b * (NSTEPS + KDD - 1) + jj] = acc;
    }
}

// ---------------- host ----------------
extern "C" void kernel_launch(void* const* d_in, const int* in_sizes, int n_in,
                              void* d_out, int out_size) {
    const float* x       = (const float*)d_in[0];
    const float* conv_w  = (const float*)d_in[1];
    const float* conv_b  = (const float*)d_in[2];
    const float* Wih0    = (const float*)d_in[3];
    const float* Whh0    = (const float*)d_in[4];
    const float* bih0    = (const float*)d_in[5];
    const float* bhh0    = (const float*)d_in[6];
    const float* Wih1    = (const float*)d_in[7];
    const float* Whh1    = (const float*)d_in[8];
    const float* bih1    = (const float*)d_in[9];
    const float* bhh1    = (const float*)d_in[10];
    const float* dec_w   = (const float*)d_in[11];
    const float* dec_b   = (const float*)d_in[12];
    const float* deconvw = (const float*)d_in[13];

    cudaFuncSetAttribute(lstm_step_kernel,
                         cudaFuncAttributeMaxDynamicSharedMemorySize, 73728);

    float *seq, *state, *yb, *W0p, *W1p, *b0p, *b1p;
    cudaGetSymbolAddress((void**)&seq,  g_seq);
    cudaGetSymbolAddress((void**)&state, g_state);
    cudaGetSymbolAddress((void**)&yb,   g_y);
    cudaGetSymbolAddress((void**)&W0p,  g_W0p);
    cudaGetSymbolAddress((void**)&W1p,  g_W1p);
    cudaGetSymbolAddress((void**)&b0p,  g_b0p);
    cudaGetSymbolAddress((void**)&b1p,  g_b1p);

    float* h0[2] = { state,          state + BH };
    float* c0    =   state + 2 * BH;
    float* h1[2] = { state + 3 * BH, state + 4 * BH };
    float* c1    =   state + 5 * BH;

    zero_state_kernel<<<(6 * BH + 255) / 256, 256>>>();
    conv_kernel<<<B_SZ, 256>>>(x, conv_w, conv_b);
    pack_w0_kernel<<<(G4 * 544 + 255) / 256, 256>>>(Wih0, Whh0, bih0, bhh0);
    pack_w1_kernel<<<(G4 * 1024 + 255) / 256, 256>>>(Wih1, Whh1, bih1, bhh1);
    pack_dec_kernel<<<(HID * FEAT + 255) / 256, 256>>>(dec_w);

    dim3 sgrid(16, 8), sblk(256);
    const size_t smem = 73728;

    for (int t = 0; t < TSTEPS; t++) {
        lstm_step_kernel<<<sgrid, sblk, smem>>>(seq + (size_t)t * B_SZ * FEAT, FEAT,
                                                h0[t & 1], 544, W0p, b0p, c0, h0[(t + 1) & 1]);
        lstm_step_kernel<<<sgrid, sblk, smem>>>(h0[(t + 1) & 1], HID,
                                                h1[t & 1], 1024, W1p, b1p, c1, h1[(t + 1) & 1]);
    }

    // y0 = h1_final @ dec_w^T + dec_b   (TSTEPS even -> final parity 0)
    dec_out_kernel<<<128, 256>>>(h1[0], yb, dec_b, -1);

    for (int s = 0; s < NSTEPS; s++) {
        lstm_step_kernel<<<sgrid, sblk, smem>>>(yb, FEAT,
                                                h0[s & 1], 544, W0p, b0p, c0, h0[(s + 1) & 1]);
        lstm_step_kernel<<<sgrid, sblk, smem>>>(h0[(s + 1) & 1], HID,
                                                h1[s & 1], 1024, W1p, b1p, c1, h1[(s + 1) & 1]);
        dec_out_kernel<<<128, 256>>>(h1[(s + 1) & 1], yb, dec_b, s);
    }

    deconv_kernel<<<B_SZ, 64>>>(deconvw, (float*)d_out);
}